// round 14
// baseline (speedup 1.0000x reference)
#include <cuda_runtime.h>
#include <math.h>

#define TT 1024
#define BB 32
#define II 512
#define HH 512
#define NG 2048   // 4*H

// ---------------------------------------------------------------------------
// Scratch (allocation-free rule: __device__ globals)
// ---------------------------------------------------------------------------
__device__ __align__(16) float g_gates[(size_t)TT * BB * NG]; // 268MB x-projection
__device__ __align__(16) float g_hbuf[2][BB * HH];            // h double buffer
// one flag per CTA, padded to 128B so polls spread across L2 lines/slices
__device__ volatile unsigned int g_arrive2[128 * 32];

// packed fp32x2 FMA (FFMA2) — PTX-only, 2 FMAs per instruction
__device__ __forceinline__ unsigned long long ffma2(
    unsigned long long a, unsigned long long b, unsigned long long c) {
    unsigned long long d;
    asm("fma.rn.f32x2 %0, %1, %2, %3;" : "=l"(d) : "l"(a), "l"(b), "l"(c));
    return d;
}
__device__ __forceinline__ unsigned long long dup2(float x) {
    unsigned long long d;
    asm("mov.b64 %0, {%1, %1};" : "=l"(d) : "f"(x));
    return d;
}
union U2 { unsigned long long u; float2 f; };

__device__ __forceinline__ void cp16(unsigned int dst_smem, const void* src) {
    asm volatile("cp.async.cg.shared.global [%0], [%1], 16;"
                 :: "r"(dst_smem), "l"(src));
}
__device__ __forceinline__ unsigned ld_acq(const volatile unsigned* p) {
    unsigned v;
    asm volatile("ld.acquire.gpu.global.u32 %0, [%1];"
                 : "=r"(v) : "l"((const unsigned*)p) : "memory");
    return v;
}
__device__ __forceinline__ void st_rel(volatile unsigned* p, unsigned v) {
    asm volatile("st.release.gpu.global.u32 [%0], %1;"
                 :: "l"((unsigned*)p), "r"(v) : "memory");
}

// ---------------------------------------------------------------------------
// init: h0 -> buffer 0, reset flags (graph-replay safe)
// ---------------------------------------------------------------------------
__global__ void init_kernel(const float* __restrict__ h0) {
    int t = blockIdx.x * blockDim.x + threadIdx.x;
    if (t < BB * HH) g_hbuf[0][t] = h0[t];
    if (t < 128 * 32) g_arrive2[t] = 0u;
}

// ---------------------------------------------------------------------------
// gates_x[L=32768][2048] = X[L][512] @ W_ih[2048][512]^T + (b_ih + b_hh)
// f32x2 core: 16 FFMA2 + 4 dup-packs per k.
// ---------------------------------------------------------------------------
__global__ __launch_bounds__(256) void gemm_x_kernel(
    const float* __restrict__ X, const float* __restrict__ W,
    const float* __restrict__ bih, const float* __restrict__ bhh)
{
    __shared__ float As[32][132];   // [k][m]
    __shared__ float Bs[32][68];    // [k][n]
    const int tid = threadIdx.x;
    const int tx = tid & 15, ty = tid >> 4;
    const int m0 = blockIdx.x * 128, n0 = blockIdx.y * 64;

    unsigned long long acc[4][4];
#pragma unroll
    for (int i = 0; i < 4; i++)
#pragma unroll
        for (int j = 0; j < 4; j++) acc[i][j] = 0ull;

    for (int k0 = 0; k0 < II; k0 += 32) {
#pragma unroll
        for (int i = 0; i < 4; i++) {
            int q = tid + i * 256;
            int r = q >> 3, c4 = (q & 7) * 4;
            float4 v = *(const float4*)&X[(size_t)(m0 + r) * II + k0 + c4];
            As[c4 + 0][r] = v.x; As[c4 + 1][r] = v.y;
            As[c4 + 2][r] = v.z; As[c4 + 3][r] = v.w;
        }
#pragma unroll
        for (int i = 0; i < 2; i++) {
            int q = tid + i * 256;
            int r = q >> 3, c4 = (q & 7) * 4;
            float4 v = *(const float4*)&W[(size_t)(n0 + r) * II + k0 + c4];
            Bs[c4 + 0][r] = v.x; Bs[c4 + 1][r] = v.y;
            Bs[c4 + 2][r] = v.z; Bs[c4 + 3][r] = v.w;
        }
        __syncthreads();
#pragma unroll
        for (int k = 0; k < 32; k++) {
            ulonglong2 a01 = *(const ulonglong2*)&As[k][ty * 8];
            ulonglong2 a23 = *(const ulonglong2*)&As[k][ty * 8 + 4];
            float4 b = *(const float4*)&Bs[k][tx * 4];
            unsigned long long bd0 = dup2(b.x), bd1 = dup2(b.y);
            unsigned long long bd2 = dup2(b.z), bd3 = dup2(b.w);
            acc[0][0] = ffma2(a01.x, bd0, acc[0][0]);
            acc[0][1] = ffma2(a01.x, bd1, acc[0][1]);
            acc[0][2] = ffma2(a01.x, bd2, acc[0][2]);
            acc[0][3] = ffma2(a01.x, bd3, acc[0][3]);
            acc[1][0] = ffma2(a01.y, bd0, acc[1][0]);
            acc[1][1] = ffma2(a01.y, bd1, acc[1][1]);
            acc[1][2] = ffma2(a01.y, bd2, acc[1][2]);
            acc[1][3] = ffma2(a01.y, bd3, acc[1][3]);
            acc[2][0] = ffma2(a23.x, bd0, acc[2][0]);
            acc[2][1] = ffma2(a23.x, bd1, acc[2][1]);
            acc[2][2] = ffma2(a23.x, bd2, acc[2][2]);
            acc[2][3] = ffma2(a23.x, bd3, acc[2][3]);
            acc[3][0] = ffma2(a23.y, bd0, acc[3][0]);
            acc[3][1] = ffma2(a23.y, bd1, acc[3][1]);
            acc[3][2] = ffma2(a23.y, bd2, acc[3][2]);
            acc[3][3] = ffma2(a23.y, bd3, acc[3][3]);
        }
        __syncthreads();
    }

    const int gn = n0 + tx * 4;
    const float b0 = bih[gn + 0] + bhh[gn + 0];
    const float b1 = bih[gn + 1] + bhh[gn + 1];
    const float b2 = bih[gn + 2] + bhh[gn + 2];
    const float b3 = bih[gn + 3] + bhh[gn + 3];
#pragma unroll
    for (int i = 0; i < 4; i++) {
        U2 u0, u1, u2, u3;
        u0.u = acc[i][0]; u1.u = acc[i][1]; u2.u = acc[i][2]; u3.u = acc[i][3];
        float4 lo = make_float4(u0.f.x + b0, u1.f.x + b1, u2.f.x + b2, u3.f.x + b3);
        float4 hi = make_float4(u0.f.y + b0, u1.f.y + b1, u2.f.y + b2, u3.f.y + b3);
        *(float4*)&g_gates[(size_t)(m0 + ty * 8 + 2 * i + 0) * NG + gn] = lo;
        *(float4*)&g_gates[(size_t)(m0 + ty * 8 + 2 * i + 1) * NG + gn] = hi;
    }
}

// ---------------------------------------------------------------------------
// Persistent recurrence v11 = v10 + per-warp dataflow gating with COALESCED
// per-warp slice staging (v7 logic, staging pattern fixed):
// warp wid consumes hidden units [64wid,64wid+64) = CTAs [16wid,16wid+16);
// polls those 16 padded flags, stages its 8KB slice with frag mapping
// (batch=frag>>4, 256B runs -> 4 cache lines per cp.async instr), GEMMs
// without any CTA-wide pre-GEMM sync. Publish via syncthreads + st.release.
// ---------------------------------------------------------------------------
#define SSTR 516
#define PSTR 40
#define SW_OFF 0
#define SH_OFF (16 * SSTR)                  // 8256
#define SP_OFF (SH_OFF + 32 * SSTR)         // 24768
#define SGX_OFF (SP_OFF + 8 * 16 * PSTR)    // +5120
#define SM_FLOATS (SGX_OFF + 128 * 4)       // 30400 floats = 121600 B

__global__ __launch_bounds__(256, 1) void lstm_rec_kernel(
    const float* __restrict__ Whh, const float* __restrict__ c0,
    float* __restrict__ out)
{
    extern __shared__ float sm[];
    float* sw  = sm + SW_OFF;    // [16][516] gate rows
    float* sh  = sm + SH_OFF;    // [32][516] h
    float* sp  = sm + SP_OFF;    // [8][16][40] K-partials
    float* sgx = sm + SGX_OFF;   // [4][32][4] x-projection gates

    const int tid  = threadIdx.x;
    const int bid  = blockIdx.x;
    const int hid0 = bid * 4;

    const int lane = tid & 31;
    const int wid  = tid >> 5;      // k-slice 0..7
    const int bq   = lane & 7;      // batch base
    const int rq   = lane >> 3;     // row base (rows rq,4+rq,8+rq,12+rq)
    const int k0   = wid * 64;

    // elementwise mapping (tid < 128)
    const int b_e  = tid >> 2;
    const int hh_e = tid & 3;

    // gx loader mapping (tid < 128)
    const int b_l = tid & 31;
    const int g_l = tid >> 5;

    // Stage W rows into SMEM once
    for (int q = tid; q < 16 * 128; q += 256) {
        int j = q >> 7; int c4 = (q & 127) * 4;
        int g = j >> 2, hh = j & 3;
        float4 v = *(const float4*)&Whh[(size_t)(g * HH + hid0 + hh) * HH + c4];
        *(float4*)&sw[j * SSTR + c4] = v;
    }

    float c_state = (tid < 128) ? c0[b_e * HH + hid0 + hh_e] : 0.f;
    float h_last = 0.f;

    // gx prefetch for step 0 (gemm_x completed before this kernel started)
    float4 gxr = make_float4(0.f, 0.f, 0.f, 0.f);
    if (tid < 128)
        gxr = *(const float4*)&g_gates[((size_t)0 * BB + b_l) * NG + g_l * 512 + hid0];

    const float* wbase = sw + rq * SSTR + k0;
    const float* hbase = sh + bq * SSTR + k0;

    // per-warp slice staging addresses: frag = i*32+lane, batch=frag>>4,
    // koff=(frag&15)*4 floats -> two contiguous 256B runs per instruction
    unsigned int sl_dst[16];
    int sl_src[16];
#pragma unroll
    for (int i = 0; i < 16; i++) {
        int frag = i * 32 + lane;
        int b = frag >> 4, ko = (frag & 15) * 4;
        sl_dst[i] = (unsigned int)__cvta_generic_to_shared(&sh[b * SSTR + k0 + ko]);
        sl_src[i] = b * HH + k0 + ko;
    }

    // this warp's producer flags (padded): CTA (16*wid + lane), lane<16
    const int flag_idx = (wid * 16 + (lane & 15)) * 32;

    __syncthreads();

    for (int s = 0; s < TT; s++) {
        // publish gx[s] to SMEM; prefetch gx[s+1]
        // (ordered vs reduction reads by the sp-syncthreads below; vs prior
        //  reduction reads by the post-cell syncthreads of step s-1)
        if (tid < 128) {
            *(float4*)&sgx[(g_l * 32 + b_l) * 4] = gxr;
            if (s + 1 < TT)
                gxr = *(const float4*)&g_gates[((size_t)(s + 1) * BB + b_l) * NG + g_l * 512 + hid0];
        }

        // ---- per-warp gate: wait for this k-slice's 16 producer CTAs ----
        if (lane < 16) {
            while (ld_acq(&g_arrive2[flag_idx]) < (unsigned)s) { }
        }
        __syncwarp();

        // ---- per-warp: stage own 8KB h-slice (coalesced fragments) ----
        const float* hsrc = g_hbuf[s & 1];
#pragma unroll
        for (int i = 0; i < 16; i++)
            cp16(sl_dst[i], hsrc + sl_src[i]);
        asm volatile("cp.async.commit_group;");
        asm volatile("cp.async.wait_group 0;" ::: "memory");
        __syncwarp();

        // ---- recurrent GEMM: 4 rows x 4 batches x 64 k per thread ----
        unsigned long long acc[4][4][2];
#pragma unroll
        for (int i = 0; i < 4; i++)
#pragma unroll
            for (int j = 0; j < 4; j++) { acc[i][j][0] = 0ull; acc[i][j][1] = 0ull; }

#pragma unroll 2
        for (int kb = 0; kb < 64; kb += 4) {
            ulonglong2 w0 = *(const ulonglong2*)(wbase + 0 * 4 * SSTR + kb);
            ulonglong2 w1 = *(const ulonglong2*)(wbase + 1 * 4 * SSTR + kb);
            ulonglong2 w2 = *(const ulonglong2*)(wbase + 2 * 4 * SSTR + kb);
            ulonglong2 w3 = *(const ulonglong2*)(wbase + 3 * 4 * SSTR + kb);
            ulonglong2 h0 = *(const ulonglong2*)(hbase + 0 * 8 * SSTR + kb);
            ulonglong2 h1 = *(const ulonglong2*)(hbase + 1 * 8 * SSTR + kb);
            ulonglong2 h2 = *(const ulonglong2*)(hbase + 2 * 8 * SSTR + kb);
            ulonglong2 h3 = *(const ulonglong2*)(hbase + 3 * 8 * SSTR + kb);
            acc[0][0][0] = ffma2(w0.x, h0.x, acc[0][0][0]);
            acc[0][0][1] = ffma2(w0.y, h0.y, acc[0][0][1]);
            acc[0][1][0] = ffma2(w0.x, h1.x, acc[0][1][0]);
            acc[0][1][1] = ffma2(w0.y, h1.y, acc[0][1][1]);
            acc[0][2][0] = ffma2(w0.x, h2.x, acc[0][2][0]);
            acc[0][2][1] = ffma2(w0.y, h2.y, acc[0][2][1]);
            acc[0][3][0] = ffma2(w0.x, h3.x, acc[0][3][0]);
            acc[0][3][1] = ffma2(w0.y, h3.y, acc[0][3][1]);
            acc[1][0][0] = ffma2(w1.x, h0.x, acc[1][0][0]);
            acc[1][0][1] = ffma2(w1.y, h0.y, acc[1][0][1]);
            acc[1][1][0] = ffma2(w1.x, h1.x, acc[1][1][0]);
            acc[1][1][1] = ffma2(w1.y, h1.y, acc[1][1][1]);
            acc[1][2][0] = ffma2(w1.x, h2.x, acc[1][2][0]);
            acc[1][2][1] = ffma2(w1.y, h2.y, acc[1][2][1]);
            acc[1][3][0] = ffma2(w1.x, h3.x, acc[1][3][0]);
            acc[1][3][1] = ffma2(w1.y, h3.y, acc[1][3][1]);
            acc[2][0][0] = ffma2(w2.x, h0.x, acc[2][0][0]);
            acc[2][0][1] = ffma2(w2.y, h0.y, acc[2][0][1]);
            acc[2][1][0] = ffma2(w2.x, h1.x, acc[2][1][0]);
            acc[2][1][1] = ffma2(w2.y, h1.y, acc[2][1][1]);
            acc[2][2][0] = ffma2(w2.x, h2.x, acc[2][2][0]);
            acc[2][2][1] = ffma2(w2.y, h2.y, acc[2][2][1]);
            acc[2][3][0] = ffma2(w2.x, h3.x, acc[2][3][0]);
            acc[2][3][1] = ffma2(w2.y, h3.y, acc[2][3][1]);
            acc[3][0][0] = ffma2(w3.x, h0.x, acc[3][0][0]);
            acc[3][0][1] = ffma2(w3.y, h0.y, acc[3][0][1]);
            acc[3][1][0] = ffma2(w3.x, h1.x, acc[3][1][0]);
            acc[3][1][1] = ffma2(w3.y, h1.y, acc[3][1][1]);
            acc[3][2][0] = ffma2(w3.x, h2.x, acc[3][2][0]);
            acc[3][2][1] = ffma2(w3.y, h2.y, acc[3][2][1]);
            acc[3][3][0] = ffma2(w3.x, h3.x, acc[3][3][0]);
            acc[3][3][1] = ffma2(w3.y, h3.y, acc[3][3][1]);
        }
#pragma unroll
        for (int i = 0; i < 4; i++)
#pragma unroll
            for (int j = 0; j < 4; j++) {
                U2 u0, u1; u0.u = acc[i][j][0]; u1.u = acc[i][j][1];
                sp[(wid * 16 + rq + 4 * i) * PSTR + (bq + 8 * j)] =
                    (u0.f.x + u0.f.y) + (u1.f.x + u1.f.y);
            }
        __syncthreads();   // join all warps' sp stores (= CTA done reading sh)

        // ---- fused K-reduction + elementwise LSTM cell (tid < 128) ----
        float hn = 0.f;
        if (tid < 128) {
            float gi = sgx[(0 * 32 + b_e) * 4 + hh_e];
            float gf = sgx[(1 * 32 + b_e) * 4 + hh_e];
            float gg = sgx[(2 * 32 + b_e) * 4 + hh_e];
            float go = sgx[(3 * 32 + b_e) * 4 + hh_e];
#pragma unroll
            for (int k = 0; k < 8; k++) {
                gi += sp[(k * 16 + 0  + hh_e) * PSTR + b_e];
                gf += sp[(k * 16 + 4  + hh_e) * PSTR + b_e];
                gg += sp[(k * 16 + 8  + hh_e) * PSTR + b_e];
                go += sp[(k * 16 + 12 + hh_e) * PSTR + b_e];
            }
            gi = 1.f / (1.f + __expf(-gi));
            gf = 1.f / (1.f + __expf(-gf));
            gg = tanhf(gg);
            go = 1.f / (1.f + __expf(-go));
            c_state = fmaf(gf, c_state, gi * gg);
            hn = go * tanhf(c_state);
            h_last = hn;
            g_hbuf[(s + 1) & 1][b_e * HH + hid0 + hh_e] = hn;
        }

        // ---- publish: syncthreads (h stores done CTA-wide) + release ----
        __syncthreads();
        if (tid == 0) st_rel(&g_arrive2[bid * 32], (unsigned)(s + 1));
        // out store off the critical path (after flag publish)
        if (tid < 128)
            out[((size_t)s * BB + b_e) * HH + hid0 + hh_e] = hn;
    }

    if (tid < 128) {
        out[(size_t)TT * BB * HH + b_e * HH + hid0 + hh_e] = h_last;
        out[(size_t)TT * BB * HH + BB * HH + b_e * HH + hid0 + hh_e] = c_state;
    }
}

// ---------------------------------------------------------------------------
extern "C" void kernel_launch(void* const* d_in, const int* in_sizes, int n_in,
                              void* d_out, int out_size) {
    const float* X   = (const float*)d_in[0];
    const float* h0  = (const float*)d_in[1];
    const float* c0  = (const float*)d_in[2];
    const float* Wih = (const float*)d_in[3];
    const float* Whh = (const float*)d_in[4];
    const float* bih = (const float*)d_in[5];
    const float* bhh = (const float*)d_in[6];
    float* out = (float*)d_out;

    cudaFuncSetAttribute(lstm_rec_kernel,
                         cudaFuncAttributeMaxDynamicSharedMemorySize,
                         SM_FLOATS * sizeof(float));

    init_kernel<<<64, 256>>>(h0);
    gemm_x_kernel<<<dim3(256, 32), 256>>>(X, Wih, bih, bhh);
    lstm_rec_kernel<<<128, 256, SM_FLOATS * sizeof(float)>>>(Whh, c0, out);
}

// round 16
// speedup vs baseline: 1.1298x; 1.1298x over previous
#include <cuda_runtime.h>
#include <math.h>

#define TT 1024
#define BB 32
#define II 512
#define HH 512
#define NG 2048   // 4*H

// ---------------------------------------------------------------------------
// Scratch (allocation-free rule: __device__ globals)
// ---------------------------------------------------------------------------
__device__ __align__(16) float g_gates[(size_t)TT * BB * NG]; // 268MB x-projection
__device__ __align__(16) float g_hbuf[2][BB * HH];            // h double buffer
// one flag per CTA, padded to 128B so polls spread across L2 lines/slices
__device__ volatile unsigned int g_arrive2[128 * 32];

// packed fp32x2 FMA (FFMA2) — PTX-only, 2 FMAs per instruction
__device__ __forceinline__ unsigned long long ffma2(
    unsigned long long a, unsigned long long b, unsigned long long c) {
    unsigned long long d;
    asm("fma.rn.f32x2 %0, %1, %2, %3;" : "=l"(d) : "l"(a), "l"(b), "l"(c));
    return d;
}
__device__ __forceinline__ unsigned long long dup2(float x) {
    unsigned long long d;
    asm("mov.b64 %0, {%1, %1};" : "=l"(d) : "f"(x));
    return d;
}
union U2 { unsigned long long u; float2 f; };

__device__ __forceinline__ void cp16(unsigned int dst_smem, const void* src) {
    asm volatile("cp.async.cg.shared.global [%0], [%1], 16;"
                 :: "r"(dst_smem), "l"(src));
}

// ---------------------------------------------------------------------------
// gates_x[L=32768][2048] = X[L][512] @ W_ih[2048][512]^T + (b_ih + b_hh)
// f32x2 core. Block (0,0) additionally performs the init work (h0 copy +
// flag reset) — runs before lstm_rec by stream order.
// ---------------------------------------------------------------------------
__global__ __launch_bounds__(256) void gemm_x_kernel(
    const float* __restrict__ X, const float* __restrict__ W,
    const float* __restrict__ bih, const float* __restrict__ bhh,
    const float* __restrict__ h0)
{
    __shared__ float As[32][132];   // [k][m]
    __shared__ float Bs[32][68];    // [k][n]
    const int tid = threadIdx.x;
    const int tx = tid & 15, ty = tid >> 4;
    const int m0 = blockIdx.x * 128, n0 = blockIdx.y * 64;

    if (blockIdx.x == 0 && blockIdx.y == 0) {
        for (int t = tid; t < BB * HH; t += 256) g_hbuf[0][t] = h0[t];
        for (int t = tid; t < 128 * 32; t += 256) g_arrive2[t] = 0u;
    }

    unsigned long long acc[4][4];
#pragma unroll
    for (int i = 0; i < 4; i++)
#pragma unroll
        for (int j = 0; j < 4; j++) acc[i][j] = 0ull;

    for (int k0 = 0; k0 < II; k0 += 32) {
#pragma unroll
        for (int i = 0; i < 4; i++) {
            int q = tid + i * 256;
            int r = q >> 3, c4 = (q & 7) * 4;
            float4 v = *(const float4*)&X[(size_t)(m0 + r) * II + k0 + c4];
            As[c4 + 0][r] = v.x; As[c4 + 1][r] = v.y;
            As[c4 + 2][r] = v.z; As[c4 + 3][r] = v.w;
        }
#pragma unroll
        for (int i = 0; i < 2; i++) {
            int q = tid + i * 256;
            int r = q >> 3, c4 = (q & 7) * 4;
            float4 v = *(const float4*)&W[(size_t)(n0 + r) * II + k0 + c4];
            Bs[c4 + 0][r] = v.x; Bs[c4 + 1][r] = v.y;
            Bs[c4 + 2][r] = v.z; Bs[c4 + 3][r] = v.w;
        }
        __syncthreads();
#pragma unroll
        for (int k = 0; k < 32; k++) {
            ulonglong2 a01 = *(const ulonglong2*)&As[k][ty * 8];
            ulonglong2 a23 = *(const ulonglong2*)&As[k][ty * 8 + 4];
            float4 b = *(const float4*)&Bs[k][tx * 4];
            unsigned long long bd0 = dup2(b.x), bd1 = dup2(b.y);
            unsigned long long bd2 = dup2(b.z), bd3 = dup2(b.w);
            acc[0][0] = ffma2(a01.x, bd0, acc[0][0]);
            acc[0][1] = ffma2(a01.x, bd1, acc[0][1]);
            acc[0][2] = ffma2(a01.x, bd2, acc[0][2]);
            acc[0][3] = ffma2(a01.x, bd3, acc[0][3]);
            acc[1][0] = ffma2(a01.y, bd0, acc[1][0]);
            acc[1][1] = ffma2(a01.y, bd1, acc[1][1]);
            acc[1][2] = ffma2(a01.y, bd2, acc[1][2]);
            acc[1][3] = ffma2(a01.y, bd3, acc[1][3]);
            acc[2][0] = ffma2(a23.x, bd0, acc[2][0]);
            acc[2][1] = ffma2(a23.x, bd1, acc[2][1]);
            acc[2][2] = ffma2(a23.x, bd2, acc[2][2]);
            acc[2][3] = ffma2(a23.x, bd3, acc[2][3]);
            acc[3][0] = ffma2(a23.y, bd0, acc[3][0]);
            acc[3][1] = ffma2(a23.y, bd1, acc[3][1]);
            acc[3][2] = ffma2(a23.y, bd2, acc[3][2]);
            acc[3][3] = ffma2(a23.y, bd3, acc[3][3]);
        }
        __syncthreads();
    }

    const int gn = n0 + tx * 4;
    const float b0 = bih[gn + 0] + bhh[gn + 0];
    const float b1 = bih[gn + 1] + bhh[gn + 1];
    const float b2 = bih[gn + 2] + bhh[gn + 2];
    const float b3 = bih[gn + 3] + bhh[gn + 3];
#pragma unroll
    for (int i = 0; i < 4; i++) {
        U2 u0, u1, u2, u3;
        u0.u = acc[i][0]; u1.u = acc[i][1]; u2.u = acc[i][2]; u3.u = acc[i][3];
        float4 lo = make_float4(u0.f.x + b0, u1.f.x + b1, u2.f.x + b2, u3.f.x + b3);
        float4 hi = make_float4(u0.f.y + b0, u1.f.y + b1, u2.f.y + b2, u3.f.y + b3);
        *(float4*)&g_gates[(size_t)(m0 + ty * 8 + 2 * i + 0) * NG + gn] = lo;
        *(float4*)&g_gates[(size_t)(m0 + ty * 8 + 2 * i + 1) * NG + gn] = hi;
    }
}

// ---------------------------------------------------------------------------
// Persistent recurrence v12 = v10 + PER-THREAD producer gating:
// thread tid's 16 staged fragments all have k-offset 4*(tid&127), i.e. they
// are produced by exactly CTA (tid&127). Each thread polls only that padded
// flag, then stages its own fragments (pattern/coalescing identical to v10).
// The pre-GEMM wait_group+syncthreads joins all threads, so all flags have
// transitively passed before any sh read. One syncthreads removed.
// ---------------------------------------------------------------------------
#define SSTR 516
#define PSTR 40
#define SW_OFF 0
#define SH_OFF (16 * SSTR)                  // 8256
#define SP_OFF (SH_OFF + 32 * SSTR)         // 24768
#define SGX_OFF (SP_OFF + 8 * 16 * PSTR)    // +5120
#define SM_FLOATS (SGX_OFF + 128 * 4)       // 30400 floats = 121600 B

__global__ __launch_bounds__(256, 1) void lstm_rec_kernel(
    const float* __restrict__ Whh, const float* __restrict__ c0,
    float* __restrict__ out)
{
    extern __shared__ float sm[];
    float* sw  = sm + SW_OFF;    // [16][516] gate rows
    float* sh  = sm + SH_OFF;    // [32][516] h
    float* sp  = sm + SP_OFF;    // [8][16][40] K-partials
    float* sgx = sm + SGX_OFF;   // [4][32][4] x-projection gates

    const int tid  = threadIdx.x;
    const int bid  = blockIdx.x;
    const int hid0 = bid * 4;

    const int lane = tid & 31;
    const int wid  = tid >> 5;      // k-slice 0..7
    const int bq   = lane & 7;      // batch base
    const int rq   = lane >> 3;     // row base (rows rq,4+rq,8+rq,12+rq)
    const int k0   = wid * 64;

    // elementwise mapping (tid < 128)
    const int b_e  = tid >> 2;
    const int hh_e = tid & 3;

    // gx loader mapping (tid < 128)
    const int b_l = tid & 31;
    const int g_l = tid >> 5;

    // Stage W rows into SMEM once
    for (int q = tid; q < 16 * 128; q += 256) {
        int j = q >> 7; int c4 = (q & 127) * 4;
        int g = j >> 2, hh = j & 3;
        float4 v = *(const float4*)&Whh[(size_t)(g * HH + hid0 + hh) * HH + c4];
        *(float4*)&sw[j * SSTR + c4] = v;
    }

    float c_state = (tid < 128) ? c0[b_e * HH + hid0 + hh_e] : 0.f;
    float h_last = 0.f;

    // gx prefetch for step 0 (gemm_x completed before this kernel started)
    float4 gxr = make_float4(0.f, 0.f, 0.f, 0.f);
    if (tid < 128)
        gxr = *(const float4*)&g_gates[((size_t)0 * BB + b_l) * NG + g_l * 512 + hid0];

    const float* wbase = sw + rq * SSTR + k0;
    const float* hbase = sh + bq * SSTR + k0;

    // staging smem addresses (coalesced; thread's frags all have
    // k-offset 4*(tid&127) -> single producer CTA = tid&127)
    unsigned int sh_dst[16];
#pragma unroll
    for (int i = 0; i < 16; i++) {
        int p = (tid + i * 256) * 4;
        int b = p >> 9, k = p & 511;
        sh_dst[i] = (unsigned int)__cvta_generic_to_shared(&sh[b * SSTR + k]);
    }

    // this thread's producer flag (padded to its own 128B line)
    volatile unsigned int* myflag = &g_arrive2[(tid & 127) * 32];

    __syncthreads();

    for (int s = 0; s < TT; s++) {
        // ---- per-thread gate: wait for OWN producer CTA, then stage ----
        while (*myflag < (unsigned)s) { }
        const float* hsrc = g_hbuf[s & 1];
#pragma unroll
        for (int i = 0; i < 16; i++)
            cp16(sh_dst[i], hsrc + (tid + i * 256) * 4);
        asm volatile("cp.async.commit_group;");

        // publish gx[s]; prefetch gx[s+1] while cp.async runs
        if (tid < 128) {
            *(float4*)&sgx[(g_l * 32 + b_l) * 4] = gxr;
            if (s + 1 < TT)
                gxr = *(const float4*)&g_gates[((size_t)(s + 1) * BB + b_l) * NG + g_l * 512 + hid0];
        }
        asm volatile("cp.async.wait_group 0;" ::: "memory");
        __syncthreads();   // joins all threads => all 128 flags >= s passed

        // ---- recurrent GEMM: 4 rows x 4 batches x 64 k per thread ----
        unsigned long long acc[4][4][2];
#pragma unroll
        for (int i = 0; i < 4; i++)
#pragma unroll
            for (int j = 0; j < 4; j++) { acc[i][j][0] = 0ull; acc[i][j][1] = 0ull; }

#pragma unroll 2
        for (int kb = 0; kb < 64; kb += 4) {
            ulonglong2 w0 = *(const ulonglong2*)(wbase + 0 * 4 * SSTR + kb);
            ulonglong2 w1 = *(const ulonglong2*)(wbase + 1 * 4 * SSTR + kb);
            ulonglong2 w2 = *(const ulonglong2*)(wbase + 2 * 4 * SSTR + kb);
            ulonglong2 w3 = *(const ulonglong2*)(wbase + 3 * 4 * SSTR + kb);
            ulonglong2 h0 = *(const ulonglong2*)(hbase + 0 * 8 * SSTR + kb);
            ulonglong2 h1 = *(const ulonglong2*)(hbase + 1 * 8 * SSTR + kb);
            ulonglong2 h2 = *(const ulonglong2*)(hbase + 2 * 8 * SSTR + kb);
            ulonglong2 h3 = *(const ulonglong2*)(hbase + 3 * 8 * SSTR + kb);
            acc[0][0][0] = ffma2(w0.x, h0.x, acc[0][0][0]);
            acc[0][0][1] = ffma2(w0.y, h0.y, acc[0][0][1]);
            acc[0][1][0] = ffma2(w0.x, h1.x, acc[0][1][0]);
            acc[0][1][1] = ffma2(w0.y, h1.y, acc[0][1][1]);
            acc[0][2][0] = ffma2(w0.x, h2.x, acc[0][2][0]);
            acc[0][2][1] = ffma2(w0.y, h2.y, acc[0][2][1]);
            acc[0][3][0] = ffma2(w0.x, h3.x, acc[0][3][0]);
            acc[0][3][1] = ffma2(w0.y, h3.y, acc[0][3][1]);
            acc[1][0][0] = ffma2(w1.x, h0.x, acc[1][0][0]);
            acc[1][0][1] = ffma2(w1.y, h0.y, acc[1][0][1]);
            acc[1][1][0] = ffma2(w1.x, h1.x, acc[1][1][0]);
            acc[1][1][1] = ffma2(w1.y, h1.y, acc[1][1][1]);
            acc[1][2][0] = ffma2(w1.x, h2.x, acc[1][2][0]);
            acc[1][2][1] = ffma2(w1.y, h2.y, acc[1][2][1]);
            acc[1][3][0] = ffma2(w1.x, h3.x, acc[1][3][0]);
            acc[1][3][1] = ffma2(w1.y, h3.y, acc[1][3][1]);
            acc[2][0][0] = ffma2(w2.x, h0.x, acc[2][0][0]);
            acc[2][0][1] = ffma2(w2.y, h0.y, acc[2][0][1]);
            acc[2][1][0] = ffma2(w2.x, h1.x, acc[2][1][0]);
            acc[2][1][1] = ffma2(w2.y, h1.y, acc[2][1][1]);
            acc[2][2][0] = ffma2(w2.x, h2.x, acc[2][2][0]);
            acc[2][2][1] = ffma2(w2.y, h2.y, acc[2][2][1]);
            acc[2][3][0] = ffma2(w2.x, h3.x, acc[2][3][0]);
            acc[2][3][1] = ffma2(w2.y, h3.y, acc[2][3][1]);
            acc[3][0][0] = ffma2(w3.x, h0.x, acc[3][0][0]);
            acc[3][0][1] = ffma2(w3.y, h0.y, acc[3][0][1]);
            acc[3][1][0] = ffma2(w3.x, h1.x, acc[3][1][0]);
            acc[3][1][1] = ffma2(w3.y, h1.y, acc[3][1][1]);
            acc[3][2][0] = ffma2(w3.x, h2.x, acc[3][2][0]);
            acc[3][2][1] = ffma2(w3.y, h2.y, acc[3][2][1]);
            acc[3][3][0] = ffma2(w3.x, h3.x, acc[3][3][0]);
            acc[3][3][1] = ffma2(w3.y, h3.y, acc[3][3][1]);
        }
#pragma unroll
        for (int i = 0; i < 4; i++)
#pragma unroll
            for (int j = 0; j < 4; j++) {
                U2 u0, u1; u0.u = acc[i][j][0]; u1.u = acc[i][j][1];
                sp[(wid * 16 + rq + 4 * i) * PSTR + (bq + 8 * j)] =
                    (u0.f.x + u0.f.y) + (u1.f.x + u1.f.y);
            }
        __syncthreads();

        // ---- fused K-reduction + elementwise LSTM cell (tid < 128) ----
        float hn = 0.f;
        if (tid < 128) {
            float gi = sgx[(0 * 32 + b_e) * 4 + hh_e];
            float gf = sgx[(1 * 32 + b_e) * 4 + hh_e];
            float gg = sgx[(2 * 32 + b_e) * 4 + hh_e];
            float go = sgx[(3 * 32 + b_e) * 4 + hh_e];
#pragma unroll
            for (int k = 0; k < 8; k++) {
                gi += sp[(k * 16 + 0  + hh_e) * PSTR + b_e];
                gf += sp[(k * 16 + 4  + hh_e) * PSTR + b_e];
                gg += sp[(k * 16 + 8  + hh_e) * PSTR + b_e];
                go += sp[(k * 16 + 12 + hh_e) * PSTR + b_e];
            }
            gi = 1.f / (1.f + __expf(-gi));
            gf = 1.f / (1.f + __expf(-gf));
            gg = tanhf(gg);
            go = 1.f / (1.f + __expf(-go));
            c_state = fmaf(gf, c_state, gi * gg);
            hn = go * tanhf(c_state);
            h_last = hn;
            g_hbuf[(s + 1) & 1][b_e * HH + hid0 + hh_e] = hn;
        }

        // ---- publish: fence, sync, flag store (poll happens per-thread
        //      at the top of the next iteration) ----
        __threadfence();
        __syncthreads();
        if (tid == 0) g_arrive2[bid * 32] = (unsigned)(s + 1);
        // out store off the critical path (after flag publish)
        if (tid < 128)
            out[((size_t)s * BB + b_e) * HH + hid0 + hh_e] = hn;
    }

    if (tid < 128) {
        out[(size_t)TT * BB * HH + b_e * HH + hid0 + hh_e] = h_last;
        out[(size_t)TT * BB * HH + BB * HH + b_e * HH + hid0 + hh_e] = c_state;
    }
}

// ---------------------------------------------------------------------------
extern "C" void kernel_launch(void* const* d_in, const int* in_sizes, int n_in,
                              void* d_out, int out_size) {
    const float* X   = (const float*)d_in[0];
    const float* h0  = (const float*)d_in[1];
    const float* c0  = (const float*)d_in[2];
    const float* Wih = (const float*)d_in[3];
    const float* Whh = (const float*)d_in[4];
    const float* bih = (const float*)d_in[5];
    const float* bhh = (const float*)d_in[6];
    float* out = (float*)d_out;

    cudaFuncSetAttribute(lstm_rec_kernel,
                         cudaFuncAttributeMaxDynamicSharedMemorySize,
                         SM_FLOATS * sizeof(float));

    gemm_x_kernel<<<dim3(256, 32), 256>>>(X, Wih, bih, bhh, h0);
    lstm_rec_kernel<<<128, 256, SM_FLOATS * sizeof(float)>>>(Whh, c0, out);
}